// round 15
// baseline (speedup 1.0000x reference)
#include <cuda_runtime.h>
#include <cuda_fp16.h>
#include <cstdint>

#define NN   50000
#define MAXE 800000
#define NB   196            // ceil(NN/256)
#define AST  72             // half stride (bank-conflict-free, 16B-aligned rows)

// ---------------- scratch (static device globals; no allocation) ----------------
__device__ int      g_deg[NN];          // zero-initialized at load; re-zeroed by scan each call
__device__ int      g_rowptr[NN + 1];
__device__ int      g_cursor[NN];
__device__ int      g_esrc[MAXE];
__device__ unsigned g_bstate[NB];       // lookback state: [31:30]=flag (1=agg,2=prefix), [29:0]=sum
__device__ float    g_dsinv[NN];
__device__ __half   g_feat[NN * 64];    // g = (h @ W) * dsinv[row]  (fp16)
__device__ __half   g_hbuf[NN * 64];    // layer output ping buffer  (fp16)
__device__ __half   g_Wt[3 * 64 * AST]; // per-layer W^T fp16, [n][k] stride AST

// per-block dtype consensus: read first 256 int64 slots (in-bounds for BOTH layouts)
__device__ __forceinline__ int block_detect_i64(const void* ei) {
    long long v = ((const long long*)ei)[threadIdx.x & 255];
    return __syncthreads_and(v >= 0 && v < NN);
}

// ---------------- W^T fp16 precompute: 3 blocks, one per layer ----------------
__global__ __launch_bounds__(256) void wsplit_kernel(const float* __restrict__ W0,
                                                     const float* __restrict__ W1,
                                                     const float* __restrict__ W2) {
    const float* W = (blockIdx.x == 0) ? W0 : (blockIdx.x == 1) ? W1 : W2;
    __half* dst = g_Wt + blockIdx.x * 64 * AST;
    for (int e = threadIdx.x; e < 4096; e += 256) {
        int k = e >> 6, n = e & 63;        // W row-major [k][n]
        dst[n * AST + k] = __float2half_rn(W[e]);
    }
}

// ---------------- hist: 2 edges/thread, vectorized index loads ----------------
__global__ __launch_bounds__(256) void hist_kernel(const void* __restrict__ ei, int E) {
    int is64 = block_detect_i64(ei);
    if (blockIdx.x == 0 && threadIdx.x < NB) g_bstate[threadIdx.x] = 0u;
    int e = (blockIdx.x * 256 + threadIdx.x) * 2;
    if (e < E) {
        int d0, d1 = -1;
        if (is64) {
            longlong2 p = ((const longlong2*)ei)[(E + e) >> 1];
            d0 = (int)p.x;
            if (e + 1 < E) d1 = (int)p.y;
        } else {
            int2 p = ((const int2*)ei)[(E + e) >> 1];
            d0 = p.x;
            if (e + 1 < E) d1 = p.y;
        }
        if ((unsigned)d0 < (unsigned)NN) atomicAdd(&g_deg[d0], 1);
        if ((unsigned)d1 < (unsigned)NN) atomicAdd(&g_deg[d1], 1);
    }
}

// ---------------- single-kernel decoupled-lookback scan ----------------
__global__ __launch_bounds__(256) void scan_kernel() {
    const unsigned full = 0xffffffffu;
    __shared__ int sh[8];
    __shared__ int s_prefix;
    int b = blockIdx.x, t = threadIdx.x;
    int lane = t & 31, wid = t >> 5;
    int i = b * 256 + t;

    int v = (i < NN) ? g_deg[i] : 0;

    int x = v;
#pragma unroll
    for (int d = 1; d < 32; d <<= 1) {
        int n = __shfl_up_sync(full, x, d);
        if (lane >= d) x += n;
    }
    if (lane == 31) sh[wid] = x;
    __syncthreads();
    if (wid == 0) {
        int w = (lane < 8) ? sh[lane] : 0;
#pragma unroll
        for (int d = 1; d < 8; d <<= 1) {
            int n = __shfl_up_sync(full, w, d);
            if (lane >= d) w += n;
        }
        if (lane < 8) sh[lane] = w;
    }
    __syncthreads();
    int incl = x + (wid ? sh[wid - 1] : 0);
    int S = sh[7];

    if (t == 0 && b > 0) atomicExch((int*)&g_bstate[b], (1 << 30) | S);

    if (wid == 0) {
        int running = 0;
        if (b > 0) {
            int idx = b - 1;
            while (true) {
                int j = idx - lane;
                unsigned st;
                do {
                    st = (j >= 0) ? (unsigned)atomicAdd((int*)&g_bstate[j], 0)
                                  : (2u << 30);
                } while (__any_sync(full, (st >> 30) == 0));
                int val = (int)(st & 0x3FFFFFFF);
                unsigned pm = __ballot_sync(full, (st >> 30) == 2u);
                if (pm) {
                    int firstP = __ffs(pm) - 1;
                    int contrib = (lane <= firstP) ? val : 0;
#pragma unroll
                    for (int d = 16; d; d >>= 1) contrib += __shfl_down_sync(full, contrib, d);
                    running += __shfl_sync(full, contrib, 0);
                    break;
                } else {
                    int contrib = val;
#pragma unroll
                    for (int d = 16; d; d >>= 1) contrib += __shfl_down_sync(full, contrib, d);
                    running += __shfl_sync(full, contrib, 0);
                    idx -= 32;
                }
            }
        }
        if (lane == 0) {
            atomicExch((int*)&g_bstate[b], (2 << 30) | (running + S));
            s_prefix = running;
        }
    }
    __syncthreads();

    if (i < NN) {
        int excl = s_prefix + incl - v;
        g_rowptr[i] = excl;
        g_cursor[i] = excl;
        g_dsinv[i]  = rsqrtf((float)(v + 1));
        g_deg[i]    = 0;
        if (i == NN - 1) g_rowptr[NN] = s_prefix + incl;
    }
}

// ---------------- scatter: 2 edges/thread, vectorized index loads ----------------
__global__ __launch_bounds__(256) void scatter_kernel(const void* __restrict__ ei, int E) {
    int is64 = block_detect_i64(ei);
    int e = (blockIdx.x * 256 + threadIdx.x) * 2;
    if (e < E) {
        int s0, d0, s1 = -1, d1 = -1;
        if (is64) {
            longlong2 ps = ((const longlong2*)ei)[e >> 1];
            longlong2 pd = ((const longlong2*)ei)[(E + e) >> 1];
            s0 = (int)ps.x; d0 = (int)pd.x;
            if (e + 1 < E) { s1 = (int)ps.y; d1 = (int)pd.y; }
        } else {
            int2 ps = ((const int2*)ei)[e >> 1];
            int2 pd = ((const int2*)ei)[(E + e) >> 1];
            s0 = ps.x; d0 = pd.x;
            if (e + 1 < E) { s1 = ps.y; d1 = pd.y; }
        }
        if ((unsigned)d0 < (unsigned)NN && (unsigned)s0 < (unsigned)NN) {
            int p = atomicAdd(&g_cursor[d0], 1);
            if ((unsigned)p < (unsigned)MAXE) g_esrc[p] = s0;
        }
        if ((unsigned)d1 < (unsigned)NN && (unsigned)s1 < (unsigned)NN) {
            int p = atomicAdd(&g_cursor[d1], 1);
            if ((unsigned)p < (unsigned)MAXE) g_esrc[p] = s1;
        }
    }
}

// ---------------- fp16 tensor-core GEMM: g = (A @ W) * dsinv[row] ----------------
#define GEMM_SMEM_BYTES ((128 * AST + 64 * AST) * 2)

__device__ __forceinline__ void mma_f16(float* c, unsigned a0, unsigned a1,
                                        unsigned a2, unsigned a3,
                                        unsigned b0, unsigned b1) {
    asm volatile(
        "mma.sync.aligned.m16n8k16.row.col.f32.f16.f16.f32 "
        "{%0,%1,%2,%3}, {%4,%5,%6,%7}, {%8,%9}, {%0,%1,%2,%3};"
        : "+f"(c[0]), "+f"(c[1]), "+f"(c[2]), "+f"(c[3])
        : "r"(a0), "r"(a1), "r"(a2), "r"(a3), "r"(b0), "r"(b1));
}

__global__ __launch_bounds__(256) void gemm_mma_kernel(const float* __restrict__ Ain,
                                                       int layer, int use_hbuf) {
    extern __shared__ __half smem[];
    __half* sA  = smem;                    // [128][AST] half
    __half* sWT = smem + 128 * AST;        // [n][AST] half  (W transposed)

    int t = threadIdx.x;
    int row0 = blockIdx.x * 128;

    {
        const float4* src = (const float4*)(g_Wt + layer * 64 * AST);
        float4* dst = (float4*)sWT;
        for (int i = t; i < (64 * AST) / 8; i += 256) dst[i] = src[i];
    }

    if (!use_hbuf) {
#pragma unroll
        for (int i = 0; i < 8; i++) {
            int q = t + i * 256;
            int r = q >> 4;
            int c4 = (q & 15) << 2;
            float4 v = make_float4(0.f, 0.f, 0.f, 0.f);
            int grow = row0 + r;
            if (grow < NN) v = *(const float4*)(Ain + (size_t)grow * 64 + c4);
            __half2* dst = (__half2*)(sA + r * AST + c4);
            dst[0] = __floats2half2_rn(v.x, v.y);
            dst[1] = __floats2half2_rn(v.z, v.w);
        }
    } else {
#pragma unroll
        for (int i = 0; i < 4; i++) {
            int q = t + i * 256;
            int r = q >> 3;
            int c8 = (q & 7) << 3;
            float4 v = make_float4(0.f, 0.f, 0.f, 0.f);
            int grow = row0 + r;
            if (grow < NN) v = *(const float4*)(g_hbuf + (size_t)grow * 64 + c8);
            *(float4*)(sA + r * AST + c8) = v;
        }
    }
    __syncthreads();

    int w8 = t >> 5;
    int mw = w8 >> 1, nw = w8 & 1;
    int mo = mw * 32, no = nw * 32;
    int lane = t & 31;
    int g = lane >> 2, tg = lane & 3;

    float acc[2][4][4];
#pragma unroll
    for (int i = 0; i < 2; i++)
#pragma unroll
        for (int j = 0; j < 4; j++)
#pragma unroll
            for (int c = 0; c < 4; c++) acc[i][j][c] = 0.f;

#pragma unroll
    for (int ks = 0; ks < 4; ks++) {
        int k0 = ks * 16;
        unsigned a[2][4];
#pragma unroll
        for (int i = 0; i < 2; i++) {
            const __half* r0p = sA + (mo + 16 * i + g) * AST + k0 + tg * 2;
            const __half* r1p = r0p + 8 * AST;
            a[i][0] = *(const unsigned*)r0p;
            a[i][1] = *(const unsigned*)r1p;
            a[i][2] = *(const unsigned*)(r0p + 8);
            a[i][3] = *(const unsigned*)(r1p + 8);
        }
#pragma unroll
        for (int j = 0; j < 4; j++) {
            const __half* bp = sWT + (no + 8 * j + g) * AST + k0 + tg * 2;
            unsigned b0 = *(const unsigned*)bp;
            unsigned b1 = *(const unsigned*)(bp + 8);
#pragma unroll
            for (int i = 0; i < 2; i++)
                mma_f16(acc[i][j], a[i][0], a[i][1], a[i][2], a[i][3], b0, b1);
        }
    }

    __half2* Fv = (__half2*)g_feat;
#pragma unroll
    for (int i = 0; i < 2; i++) {
        int r0 = row0 + mo + 16 * i + g;
        int r1 = r0 + 8;
        float s0 = (r0 < NN) ? g_dsinv[r0] : 0.f;
        float s1 = (r1 < NN) ? g_dsinv[r1] : 0.f;
#pragma unroll
        for (int j = 0; j < 4; j++) {
            int colh = (no + 8 * j + 2 * tg) >> 1;
            if (r0 < NN)
                Fv[r0 * 32 + colh] =
                    __floats2half2_rn(acc[i][j][0] * s0, acc[i][j][1] * s0);
            if (r1 < NN)
                Fv[r1 * 32 + colh] =
                    __floats2half2_rn(acc[i][j][2] * s1, acc[i][j][3] * s1);
        }
    }
}

// ---------------- aggregation: one warp per node, half2 CSR gather ----------------
// 8-deep MLP (R13 shape), 2 accumulator pairs to halve the FADD chain.
__global__ __launch_bounds__(256) void aggregate_kernel(const float* __restrict__ bias,
                                                        float* __restrict__ dout,
                                                        int mode) {
    int warp = (blockIdx.x * blockDim.x + threadIdx.x) >> 5;
    int lane = threadIdx.x & 31;
    if (warp >= NN) return;
    int node = warp;
    int beg = g_rowptr[node];
    int end = g_rowptr[node + 1];

    const __half2* __restrict__ Gv = (const __half2*)g_feat;
    int off = node * 32 + lane;
    float2 selfv = __half22float2(Gv[off]);       // self-loop term g[node]
    float ax0 = selfv.x, ay0 = selfv.y;
    float ax1 = 0.f, ay1 = 0.f;

    const unsigned full = 0xffffffffu;
    for (int base = beg; base < end; base += 32) {
        int idx = base + lane;
        int mysrc = (idx < end) ? g_esrc[idx] : 0;
        int cnt = min(32, end - base);
        int i = 0;
        for (; i + 8 <= cnt; i += 8) {
            int s0 = __shfl_sync(full, mysrc, i);
            int s1 = __shfl_sync(full, mysrc, i + 1);
            int s2 = __shfl_sync(full, mysrc, i + 2);
            int s3 = __shfl_sync(full, mysrc, i + 3);
            int s4 = __shfl_sync(full, mysrc, i + 4);
            int s5 = __shfl_sync(full, mysrc, i + 5);
            int s6 = __shfl_sync(full, mysrc, i + 6);
            int s7 = __shfl_sync(full, mysrc, i + 7);
            float2 v0 = __half22float2(Gv[s0 * 32 + lane]);
            float2 v1 = __half22float2(Gv[s1 * 32 + lane]);
            float2 v2 = __half22float2(Gv[s2 * 32 + lane]);
            float2 v3 = __half22float2(Gv[s3 * 32 + lane]);
            float2 v4 = __half22float2(Gv[s4 * 32 + lane]);
            float2 v5 = __half22float2(Gv[s5 * 32 + lane]);
            float2 v6 = __half22float2(Gv[s6 * 32 + lane]);
            float2 v7 = __half22float2(Gv[s7 * 32 + lane]);
            ax0 += v0.x; ay0 += v0.y; ax1 += v1.x; ay1 += v1.y;
            ax0 += v2.x; ay0 += v2.y; ax1 += v3.x; ay1 += v3.y;
            ax0 += v4.x; ay0 += v4.y; ax1 += v5.x; ay1 += v5.y;
            ax0 += v6.x; ay0 += v6.y; ax1 += v7.x; ay1 += v7.y;
        }
        for (; i < cnt; i++) {
            int s = __shfl_sync(full, mysrc, i);
            float2 v = __half22float2(Gv[s * 32 + lane]);
            ax0 += v.x; ay0 += v.y;
        }
    }

    float ax = ax0 + ax1;
    float ay = ay0 + ay1;
    float ds = g_dsinv[node];
    float2 bv = ((const float2*)bias)[lane];
    float o0 = fmaf(ds, ax, bv.x);
    float o1 = fmaf(ds, ay, bv.y);
    if (mode < 2) {
        o0 = fmaxf(o0, 0.f);
        o1 = fmaxf(o1, 0.f);
        ((__half2*)g_hbuf)[off] = __floats2half2_rn(o0, o1);
    } else {
        ((float2*)dout)[off] = make_float2(o0, o1);
    }
}

// ---------------- launch ----------------
extern "C" void kernel_launch(void* const* d_in, const int* in_sizes, int n_in,
                              void* d_out, int out_size) {
    const float* x  = (const float*)d_in[0];
    const void*  ei = d_in[1];
    const float* W0 = (const float*)d_in[2];
    const float* b0 = (const float*)d_in[3];
    const float* W1 = (const float*)d_in[4];
    const float* b1 = (const float*)d_in[5];
    const float* W2 = (const float*)d_in[6];
    const float* b2 = (const float*)d_in[7];
    float* out = (float*)d_out;

    int E = in_sizes[1] / 2;

    static int smem_set = 0;
    if (!smem_set) {
        cudaFuncSetAttribute(gemm_mma_kernel,
                             cudaFuncAttributeMaxDynamicSharedMemorySize,
                             GEMM_SMEM_BYTES);
        smem_set = 1;
    }

    int gemm_blocks = (NN + 127) / 128;
    int agg_blocks  = (NN * 32 + 255) / 256;
    int epair_blocks = (E / 2 + 255) / 256;

    wsplit_kernel<<<3, 256>>>(W0, W1, W2);                   // 1
    hist_kernel<<<epair_blocks, 256>>>(ei, E);               // 2
    scan_kernel<<<NB, 256>>>();                              // 3
    gemm_mma_kernel<<<gemm_blocks, 256, GEMM_SMEM_BYTES>>>(x, 0, 0);   // 4 -> profiled
    scatter_kernel<<<epair_blocks, 256>>>(ei, E);            // 5
    aggregate_kernel<<<agg_blocks, 256>>>(b0, out, 0);       // 6
    gemm_mma_kernel<<<gemm_blocks, 256, GEMM_SMEM_BYTES>>>(x, 1, 1);
    aggregate_kernel<<<agg_blocks, 256>>>(b1, out, 1);
    gemm_mma_kernel<<<gemm_blocks, 256, GEMM_SMEM_BYTES>>>(x, 2, 1);
    aggregate_kernel<<<agg_blocks, 256>>>(b2, out, 2);
}

// round 17
// speedup vs baseline: 1.4719x; 1.4719x over previous
#include <cuda_runtime.h>
#include <cuda_fp16.h>
#include <cstdint>

#define NN   50000
#define MAXE 800000
#define NB   196            // ceil(NN/256)
#define AST  72             // half stride (bank-conflict-free, 16B-aligned rows)

// ---------------- scratch (static device globals; no allocation) ----------------
__device__ int      g_deg[NN];          // zero-initialized at load; re-zeroed by scan each call
__device__ int      g_rowptr[NN + 1];
__device__ int      g_cursor[NN];
__device__ int      g_esrc[MAXE];
__device__ unsigned g_bstate[NB];       // lookback state: [31:30]=flag (1=agg,2=prefix), [29:0]=sum
__device__ float    g_dsinv[NN];
__device__ __half   g_feat[NN * 64];    // g = (h @ W) * dsinv[row]  (fp16)
__device__ __half   g_hbuf[NN * 64];    // layer output ping buffer  (fp16)
__device__ __half   g_Wt[3 * 64 * AST]; // per-layer W^T fp16, [n][k] stride AST

// per-block dtype consensus: read first 256 int64 slots (in-bounds for BOTH layouts)
__device__ __forceinline__ int block_detect_i64(const void* ei) {
    long long v = ((const long long*)ei)[threadIdx.x & 255];
    return __syncthreads_and(v >= 0 && v < NN);
}

// ---------------- W^T fp16 precompute: 3 blocks, one per layer ----------------
__global__ __launch_bounds__(256) void wsplit_kernel(const float* __restrict__ W0,
                                                     const float* __restrict__ W1,
                                                     const float* __restrict__ W2) {
    const float* W = (blockIdx.x == 0) ? W0 : (blockIdx.x == 1) ? W1 : W2;
    __half* dst = g_Wt + blockIdx.x * 64 * AST;
    for (int e = threadIdx.x; e < 4096; e += 256) {
        int k = e >> 6, n = e & 63;        // W row-major [k][n]
        dst[n * AST + k] = __float2half_rn(W[e]);
    }
}

// ---------------- hist: deg histogram (+ lookback-state reset by block 0) ----------------
__global__ __launch_bounds__(256) void hist_kernel(const void* __restrict__ ei, int E) {
    int is64 = block_detect_i64(ei);
    if (blockIdx.x == 0 && threadIdx.x < NB) g_bstate[threadIdx.x] = 0u;
    int e = blockIdx.x * 256 + threadIdx.x;
    if (e < E) {
        int d = is64 ? (int)((const long long*)ei)[(long long)E + e]
                     : ((const int*)ei)[(long long)E + e];
        if ((unsigned)d < (unsigned)NN) atomicAdd(&g_deg[d], 1);
    }
}

// ---------------- single-kernel decoupled-lookback scan ----------------
__global__ __launch_bounds__(256) void scan_kernel() {
    const unsigned full = 0xffffffffu;
    __shared__ int sh[8];
    __shared__ int s_prefix;
    int b = blockIdx.x, t = threadIdx.x;
    int lane = t & 31, wid = t >> 5;
    int i = b * 256 + t;

    int v = (i < NN) ? g_deg[i] : 0;

    int x = v;
#pragma unroll
    for (int d = 1; d < 32; d <<= 1) {
        int n = __shfl_up_sync(full, x, d);
        if (lane >= d) x += n;
    }
    if (lane == 31) sh[wid] = x;
    __syncthreads();
    if (wid == 0) {
        int w = (lane < 8) ? sh[lane] : 0;
#pragma unroll
        for (int d = 1; d < 8; d <<= 1) {
            int n = __shfl_up_sync(full, w, d);
            if (lane >= d) w += n;
        }
        if (lane < 8) sh[lane] = w;
    }
    __syncthreads();
    int incl = x + (wid ? sh[wid - 1] : 0);
    int S = sh[7];

    if (t == 0 && b > 0) atomicExch((int*)&g_bstate[b], (1 << 30) | S);

    if (wid == 0) {
        int running = 0;
        if (b > 0) {
            int idx = b - 1;
            while (true) {
                int j = idx - lane;
                unsigned st;
                do {
                    st = (j >= 0) ? (unsigned)atomicAdd((int*)&g_bstate[j], 0)
                                  : (2u << 30);
                } while (__any_sync(full, (st >> 30) == 0));
                int val = (int)(st & 0x3FFFFFFF);
                unsigned pm = __ballot_sync(full, (st >> 30) == 2u);
                if (pm) {
                    int firstP = __ffs(pm) - 1;
                    int contrib = (lane <= firstP) ? val : 0;
#pragma unroll
                    for (int d = 16; d; d >>= 1) contrib += __shfl_down_sync(full, contrib, d);
                    running += __shfl_sync(full, contrib, 0);
                    break;
                } else {
                    int contrib = val;
#pragma unroll
                    for (int d = 16; d; d >>= 1) contrib += __shfl_down_sync(full, contrib, d);
                    running += __shfl_sync(full, contrib, 0);
                    idx -= 32;
                }
            }
        }
        if (lane == 0) {
            atomicExch((int*)&g_bstate[b], (2 << 30) | (running + S));
            s_prefix = running;
        }
    }
    __syncthreads();

    if (i < NN) {
        int excl = s_prefix + incl - v;
        g_rowptr[i] = excl;
        g_cursor[i] = excl;
        g_dsinv[i]  = rsqrtf((float)(v + 1));
        g_deg[i]    = 0;
        if (i == NN - 1) g_rowptr[NN] = s_prefix + incl;
    }
}

// ---------------- scatter: fill CSR adjacency ----------------
__global__ __launch_bounds__(256) void scatter_kernel(const void* __restrict__ ei, int E) {
    int is64 = block_detect_i64(ei);
    int e = blockIdx.x * 256 + threadIdx.x;
    if (e < E) {
        int s, d;
        if (is64) {
            s = (int)((const long long*)ei)[e];
            d = (int)((const long long*)ei)[(long long)E + e];
        } else {
            s = ((const int*)ei)[e];
            d = ((const int*)ei)[(long long)E + e];
        }
        if ((unsigned)d < (unsigned)NN && (unsigned)s < (unsigned)NN) {
            int p = atomicAdd(&g_cursor[d], 1);
            if ((unsigned)p < (unsigned)MAXE) g_esrc[p] = s;
        }
    }
}

// ---------------- fp16 tensor-core GEMM: g = (A @ W) * dsinv[row] ----------------
#define GEMM_SMEM_BYTES ((128 * AST + 64 * AST) * 2)

__device__ __forceinline__ void mma_f16(float* c, unsigned a0, unsigned a1,
                                        unsigned a2, unsigned a3,
                                        unsigned b0, unsigned b1) {
    asm volatile(
        "mma.sync.aligned.m16n8k16.row.col.f32.f16.f16.f32 "
        "{%0,%1,%2,%3}, {%4,%5,%6,%7}, {%8,%9}, {%0,%1,%2,%3};"
        : "+f"(c[0]), "+f"(c[1]), "+f"(c[2]), "+f"(c[3])
        : "r"(a0), "r"(a1), "r"(a2), "r"(a3), "r"(b0), "r"(b1));
}

__global__ __launch_bounds__(256) void gemm_mma_kernel(const float* __restrict__ Ain,
                                                       int layer, int use_hbuf) {
    extern __shared__ __half smem[];
    __half* sA  = smem;                    // [128][AST] half
    __half* sWT = smem + 128 * AST;        // [n][AST] half  (W transposed)

    int t = threadIdx.x;
    int row0 = blockIdx.x * 128;

    {
        const float4* src = (const float4*)(g_Wt + layer * 64 * AST);
        float4* dst = (float4*)sWT;
        for (int i = t; i < (64 * AST) / 8; i += 256) dst[i] = src[i];
    }

    if (!use_hbuf) {
#pragma unroll
        for (int i = 0; i < 8; i++) {
            int q = t + i * 256;
            int r = q >> 4;
            int c4 = (q & 15) << 2;
            float4 v = make_float4(0.f, 0.f, 0.f, 0.f);
            int grow = row0 + r;
            if (grow < NN) v = *(const float4*)(Ain + (size_t)grow * 64 + c4);
            __half2* dst = (__half2*)(sA + r * AST + c4);
            dst[0] = __floats2half2_rn(v.x, v.y);
            dst[1] = __floats2half2_rn(v.z, v.w);
        }
    } else {
#pragma unroll
        for (int i = 0; i < 4; i++) {
            int q = t + i * 256;
            int r = q >> 3;
            int c8 = (q & 7) << 3;
            float4 v = make_float4(0.f, 0.f, 0.f, 0.f);
            int grow = row0 + r;
            if (grow < NN) v = *(const float4*)(g_hbuf + (size_t)grow * 64 + c8);
            *(float4*)(sA + r * AST + c8) = v;
        }
    }
    __syncthreads();

    int w8 = t >> 5;
    int mw = w8 >> 1, nw = w8 & 1;
    int mo = mw * 32, no = nw * 32;
    int lane = t & 31;
    int g = lane >> 2, tg = lane & 3;

    float acc[2][4][4];
#pragma unroll
    for (int i = 0; i < 2; i++)
#pragma unroll
        for (int j = 0; j < 4; j++)
#pragma unroll
            for (int c = 0; c < 4; c++) acc[i][j][c] = 0.f;

#pragma unroll
    for (int ks = 0; ks < 4; ks++) {
        int k0 = ks * 16;
        unsigned a[2][4];
#pragma unroll
        for (int i = 0; i < 2; i++) {
            const __half* r0p = sA + (mo + 16 * i + g) * AST + k0 + tg * 2;
            const __half* r1p = r0p + 8 * AST;
            a[i][0] = *(const unsigned*)r0p;
            a[i][1] = *(const unsigned*)r1p;
            a[i][2] = *(const unsigned*)(r0p + 8);
            a[i][3] = *(const unsigned*)(r1p + 8);
        }
#pragma unroll
        for (int j = 0; j < 4; j++) {
            const __half* bp = sWT + (no + 8 * j + g) * AST + k0 + tg * 2;
            unsigned b0 = *(const unsigned*)bp;
            unsigned b1 = *(const unsigned*)(bp + 8);
#pragma unroll
            for (int i = 0; i < 2; i++)
                mma_f16(acc[i][j], a[i][0], a[i][1], a[i][2], a[i][3], b0, b1);
        }
    }

    __half2* Fv = (__half2*)g_feat;
#pragma unroll
    for (int i = 0; i < 2; i++) {
        int r0 = row0 + mo + 16 * i + g;
        int r1 = r0 + 8;
        float s0 = (r0 < NN) ? g_dsinv[r0] : 0.f;
        float s1 = (r1 < NN) ? g_dsinv[r1] : 0.f;
#pragma unroll
        for (int j = 0; j < 4; j++) {
            int colh = (no + 8 * j + 2 * tg) >> 1;
            if (r0 < NN)
                Fv[r0 * 32 + colh] =
                    __floats2half2_rn(acc[i][j][0] * s0, acc[i][j][1] * s0);
            if (r1 < NN)
                Fv[r1 * 32 + colh] =
                    __floats2half2_rn(acc[i][j][2] * s1, acc[i][j][3] * s1);
        }
    }
}

// ---------------- aggregation: one warp per node, half2 CSR gather, 8-deep MLP ----------------
__global__ __launch_bounds__(256) void aggregate_kernel(const float* __restrict__ bias,
                                                        float* __restrict__ dout,
                                                        int mode) {
    int warp = (blockIdx.x * blockDim.x + threadIdx.x) >> 5;
    int lane = threadIdx.x & 31;
    if (warp >= NN) return;
    int node = warp;
    int beg = g_rowptr[node];
    int end = g_rowptr[node + 1];

    const __half2* __restrict__ Gv = (const __half2*)g_feat;
    int off = node * 32 + lane;
    float2 selfv = __half22float2(Gv[off]);       // self-loop term g[node]
    float ax = selfv.x, ay = selfv.y;

    const unsigned full = 0xffffffffu;
    for (int base = beg; base < end; base += 32) {
        int idx = base + lane;
        int mysrc = (idx < end) ? g_esrc[idx] : 0;
        int cnt = min(32, end - base);
        int i = 0;
        for (; i + 8 <= cnt; i += 8) {
            int s0 = __shfl_sync(full, mysrc, i);
            int s1 = __shfl_sync(full, mysrc, i + 1);
            int s2 = __shfl_sync(full, mysrc, i + 2);
            int s3 = __shfl_sync(full, mysrc, i + 3);
            int s4 = __shfl_sync(full, mysrc, i + 4);
            int s5 = __shfl_sync(full, mysrc, i + 5);
            int s6 = __shfl_sync(full, mysrc, i + 6);
            int s7 = __shfl_sync(full, mysrc, i + 7);
            float2 v0 = __half22float2(Gv[s0 * 32 + lane]);
            float2 v1 = __half22float2(Gv[s1 * 32 + lane]);
            float2 v2 = __half22float2(Gv[s2 * 32 + lane]);
            float2 v3 = __half22float2(Gv[s3 * 32 + lane]);
            float2 v4 = __half22float2(Gv[s4 * 32 + lane]);
            float2 v5 = __half22float2(Gv[s5 * 32 + lane]);
            float2 v6 = __half22float2(Gv[s6 * 32 + lane]);
            float2 v7 = __half22float2(Gv[s7 * 32 + lane]);
            ax += v0.x; ay += v0.y; ax += v1.x; ay += v1.y;
            ax += v2.x; ay += v2.y; ax += v3.x; ay += v3.y;
            ax += v4.x; ay += v4.y; ax += v5.x; ay += v5.y;
            ax += v6.x; ay += v6.y; ax += v7.x; ay += v7.y;
        }
        for (; i < cnt; i++) {
            int s = __shfl_sync(full, mysrc, i);
            float2 v = __half22float2(Gv[s * 32 + lane]);
            ax += v.x; ay += v.y;
        }
    }

    float ds = g_dsinv[node];
    float o0 = fmaf(ds, ax, bias[lane * 2]);
    float o1 = fmaf(ds, ay, bias[lane * 2 + 1]);
    if (mode < 2) {
        o0 = fmaxf(o0, 0.f);
        o1 = fmaxf(o1, 0.f);
        ((__half2*)g_hbuf)[off] = __floats2half2_rn(o0, o1);
    } else {
        ((float2*)dout)[off] = make_float2(o0, o1);
    }
}

// ---------------- launch: fork/join schedule ----------------
// stream0 (legacy): hist -> scan -> scatter -> [join] agg0 -> gemm1 -> agg1 -> gemm2 -> agg2
// stream2:          wsplit ----------> gemm0 (waits scan via event)
extern "C" void kernel_launch(void* const* d_in, const int* in_sizes, int n_in,
                              void* d_out, int out_size) {
    const float* x  = (const float*)d_in[0];
    const void*  ei = d_in[1];
    const float* W0 = (const float*)d_in[2];
    const float* b0 = (const float*)d_in[3];
    const float* W1 = (const float*)d_in[4];
    const float* b1 = (const float*)d_in[5];
    const float* W2 = (const float*)d_in[6];
    const float* b2 = (const float*)d_in[7];
    float* out = (float*)d_out;

    int E = in_sizes[1] / 2;

    static cudaStream_t s2 = nullptr;
    static cudaEvent_t evFork = nullptr, evScan = nullptr, evGemm0 = nullptr;
    if (!s2) {
        cudaFuncSetAttribute(gemm_mma_kernel,
                             cudaFuncAttributeMaxDynamicSharedMemorySize,
                             GEMM_SMEM_BYTES);
        cudaStreamCreateWithFlags(&s2, cudaStreamNonBlocking);
        cudaEventCreateWithFlags(&evFork,  cudaEventDisableTiming);
        cudaEventCreateWithFlags(&evScan,  cudaEventDisableTiming);
        cudaEventCreateWithFlags(&evGemm0, cudaEventDisableTiming);
    }

    int gemm_blocks = (NN + 127) / 128;
    int agg_blocks  = (NN * 32 + 255) / 256;
    int edge_blocks = (E + 255) / 256;

    // fork: wsplit on s2 concurrent with hist on s0
    cudaEventRecord(evFork, 0);
    cudaStreamWaitEvent(s2, evFork, 0);
    wsplit_kernel<<<3, 256, 0, s2>>>(W0, W1, W2);

    hist_kernel<<<edge_blocks, 256>>>(ei, E);
    scan_kernel<<<NB, 256>>>();
    cudaEventRecord(evScan, 0);

    // s2: gemm0 after wsplit (same stream) and scan (event)
    cudaStreamWaitEvent(s2, evScan, 0);
    gemm_mma_kernel<<<gemm_blocks, 256, GEMM_SMEM_BYTES, s2>>>(x, 0, 0);
    cudaEventRecord(evGemm0, s2);

    // s0: scatter concurrent with gemm0
    scatter_kernel<<<edge_blocks, 256>>>(ei, E);

    // join, then the serial tail on s0
    cudaStreamWaitEvent(0, evGemm0, 0);
    aggregate_kernel<<<agg_blocks, 256>>>(b0, out, 0);
    gemm_mma_kernel<<<gemm_blocks, 256, GEMM_SMEM_BYTES>>>(x, 1, 1);
    aggregate_kernel<<<agg_blocks, 256>>>(b1, out, 1);
    gemm_mma_kernel<<<gemm_blocks, 256, GEMM_SMEM_BYTES>>>(x, 2, 1);
    aggregate_kernel<<<agg_blocks, 256>>>(b2, out, 2);
}